// round 12
// baseline (speedup 1.0000x reference)
#include <cuda_runtime.h>
#include <cuda_fp16.h>
#include <cstdint>

// ---------------- problem constants ----------------
#define B_SZ   1024
#define NPOS   165
#define CCH    256
#define KTOT   1792            // 7 * 256
#define MTOT   (B_SZ * NPOS)   // 168960
#define MTILE  128
#define NTILE  128
#define MTILES (MTOT / MTILE)  // 1320 (exact)
#define KSTAGE 64
#define NSTAGES (KTOT / KSTAGE) // 28
#define PIPE   3               // cp.async ring depth

// smem: A bufs PIPE x 16KB @0, B bufs PIPE x 16KB @ PIPE*16384
#define ABUF_BYTES 16384
#define SMEM_BYTES (2 * PIPE * ABUF_BYTES)   // 98304 (96KB)

// ---------------- device globals (scratch; no runtime allocs) ----------------
__device__ __align__(16) __half g_Wt1[CCH * KTOT];
__device__ __align__(16) __half g_Wt2[CCH * KTOT];
__device__ __align__(16) __half g_xh[(size_t)MTOT * CCH];
__device__ __align__(16) __half g_h [(size_t)MTOT * CCH];

// hex neighbor offsets (0-based grid coords). DY same for both parities.
__constant__ int cDY[7]  = {-1,-1, 0,0,0, 1,1};
__constant__ int cDX0[7] = {-1, 0,-1,0,1,-1,0};  // y even (0-based)
__constant__ int cDX1[7] = { 0, 1,-1,0,1, 0,1};  // y odd  (0-based)

// ---------------- helpers ----------------
__device__ __forceinline__ uint32_t smem_to_u32(const void* p) {
    uint32_t a;
    asm("{ .reg .u64 t; cvta.to.shared.u64 t, %1; cvt.u32.u64 %0, t; }" : "=r"(a) : "l"(p));
    return a;
}
__device__ __forceinline__ void cp_async16(uint32_t dst, const void* src, uint32_t srcsize) {
    asm volatile("cp.async.cg.shared.global [%0], [%1], 16, %2;"
                 :: "r"(dst), "l"(src), "r"(srcsize));
}
#define CP_COMMIT  asm volatile("cp.async.commit_group;")
#define CP_WAIT1   asm volatile("cp.async.wait_group 1;")
#define CP_WAIT0   asm volatile("cp.async.wait_group 0;")

__device__ __forceinline__ void ldmatrix_x4(uint32_t* r, uint32_t addr) {
    asm volatile("ldmatrix.sync.aligned.m8n8.x4.shared.b16 {%0,%1,%2,%3}, [%4];"
                 : "=r"(r[0]), "=r"(r[1]), "=r"(r[2]), "=r"(r[3]) : "r"(addr));
}
__device__ __forceinline__ void mma16816(float* c, const uint32_t* a, uint32_t b0, uint32_t b1) {
    asm volatile("mma.sync.aligned.m16n8k16.row.col.f32.f16.f16.f32 "
                 "{%0,%1,%2,%3}, {%4,%5,%6,%7}, {%8,%9}, {%0,%1,%2,%3};"
                 : "+f"(c[0]), "+f"(c[1]), "+f"(c[2]), "+f"(c[3])
                 : "r"(a[0]), "r"(a[1]), "r"(a[2]), "r"(a[3]), "r"(b0), "r"(b1));
}
__device__ __forceinline__ uint32_t pack_h2(float a, float b) {
    __half2 h = __floats2half2_rn(a, b);
    return *reinterpret_cast<uint32_t*>(&h);
}
__device__ __forceinline__ float leaky(float v) { return v > 0.0f ? v : 0.01f * v; }

// ---------------- prep kernels ----------------
__global__ void prep_weights(const float* __restrict__ W1, const float* __restrict__ W2) {
    int i = blockIdx.x * 256 + threadIdx.x;
    if (i < KTOT * CCH) {
        int k = i >> 8, n = i & 255;
        g_Wt1[n * KTOT + k] = __float2half_rn(W1[i]);
        g_Wt2[n * KTOT + k] = __float2half_rn(W2[i]);
    }
}
__global__ void convert_x(const float* __restrict__ x) {
    size_t i = (size_t)blockIdx.x * 256 + threadIdx.x;   // one float4 each
    float4 f = reinterpret_cast<const float4*>(x)[i];
    uint2 o;
    o.x = pack_h2(f.x, f.y);
    o.y = pack_h2(f.z, f.w);
    reinterpret_cast<uint2*>(g_xh)[i] = o;
}

// ---------------- fused hexconv GEMM (mma.sync path) ----------------
// CONV==1: A = g_xh, out = leaky(acc + b1) -> g_h (fp16)
// CONV==2: A = g_h,  out = leaky(acc + b2 + x) -> fp32 d_out
template <int CONV>
__global__ void __launch_bounds__(256)
hexconv_kernel(const __half* __restrict__ asrc, const float* __restrict__ bias,
               const float* __restrict__ xres, float* __restrict__ outp) {
    extern __shared__ char smem[];
    const uint32_t sb = smem_to_u32(smem);
    const int tid = threadIdx.x;
    const int wid = tid >> 5, L = tid & 31;
    const int lane8 = tid & 7;      // 16B column within 128B row
    const int rowslot = tid >> 3;   // 32 rows per pass

    // ---- loader geometry: 4 rows per thread for both A (gather) and B ----
    int pb[4], yy[4], xx[4];
    uint32_t rswz[4];
#pragma unroll
    for (int j = 0; j < 4; j++) {
        int i = rowslot + 32 * j;
        int r = blockIdx.x * MTILE + i;
        int b = r / NPOS;
        int p = r - b * NPOS;
        pb[j] = b * NPOS;
        yy[j] = p / 15;
        xx[j] = p - yy[j] * 15;
        uint32_t off = (uint32_t)i * 128u + (uint32_t)lane8 * 16u;
        rswz[j] = off ^ ((off >> 3) & 0x70u);
    }
    const __half* __restrict__ Wt = (CONV == 1) ? g_Wt1 : g_Wt2;
    const int nTileBase = blockIdx.y * NTILE;

    // ---- compute-side ldmatrix lane addressing (precomputed row terms) ----
    // warps: wid%4 -> M (32 rows), wid/4 -> N (64 cols)
    const int mwb = (wid & 3) * 32;
    const int nwb = (wid >> 2) * 64;
    const uint32_t rowA = (uint32_t)(mwb + (L & 7) + ((L & 8) ? 8 : 0));
    const uint32_t kbA16 = ((uint32_t)((L >> 4) & 1)) * 16u;   // kbitA*16
    uint32_t aBase[2];   // row*128 + swizzle-phase, per m-tile
#pragma unroll
    for (int mt = 0; mt < 2; mt++) {
        uint32_t row = rowA + (uint32_t)mt * 16u;
        aBase[mt] = row * 128u + (((row & 7u) << 4) ^ kbA16);
    }
    const uint32_t kbB16 = ((uint32_t)((L >> 3) & 1)) * 16u;
    uint32_t bBase[4];
#pragma unroll
    for (int j = 0; j < 4; j++) {
        uint32_t row = (uint32_t)(nwb + j * 16 + (L & 7) + ((L & 16) ? 8 : 0));
        bBase[j] = row * 128u + (((row & 7u) << 4) ^ kbB16);
    }

    float acc[2][8][4];
#pragma unroll
    for (int mt = 0; mt < 2; mt++)
#pragma unroll
        for (int nf = 0; nf < 8; nf++)
#pragma unroll
            for (int q = 0; q < 4; q++) acc[mt][nf][q] = 0.0f;

    // ---- stage loader (cp.async, zero-fill for out-of-grid neighbors) ----
    auto loadStage = [&](int s, int buf) {
        const uint32_t Asm = sb + (uint32_t)buf * ABUF_BYTES;
        const uint32_t Bsm = sb + (uint32_t)(PIPE * ABUF_BYTES) + (uint32_t)buf * ABUF_BYTES;
        // B: W rows nTileBase+n, k in [s*64, s*64+64)
        const __half* wk = Wt + s * KSTAGE + lane8 * 8;
#pragma unroll
        for (int j = 0; j < 4; j++) {
            int n = nTileBase + rowslot + 32 * j;
            cp_async16(Bsm + rswz[j], wk + (size_t)n * KTOT, 16u);
        }
        // A: hex gather, tap = s>>2, channels (s&3)*64 ..
        const int tap = s >> 2;
        const int cc = ((s & 3) << 6) + lane8 * 8;
        const int dy = cDY[tap];
#pragma unroll
        for (int j = 0; j < 4; j++) {
            int ny = yy[j] + dy;
            int nx = xx[j] + ((yy[j] & 1) ? cDX1[tap] : cDX0[tap]);
            bool v = ((unsigned)ny < 11u) && ((unsigned)nx < 15u);
            int nrow = v ? (pb[j] + ny * 15 + nx) : 0;
            cp_async16(Asm + rswz[j], asrc + (size_t)nrow * CCH + cc, v ? 16u : 0u);
        }
    };

    // ---- stage compute: 4 x k16 steps of m16n8k16 ----
    auto computeStage = [&](int buf) {
        const uint32_t Asm = sb + (uint32_t)buf * ABUF_BYTES;
        const uint32_t Bsm = sb + (uint32_t)(PIPE * ABUF_BYTES) + (uint32_t)buf * ABUF_BYTES;
#pragma unroll
        for (int k = 0; k < 4; k++) {
            const uint32_t kOff = 32u * (uint32_t)k;   // kq*16 with kq=2k (xor-phase folded into bases)
            // batch all LDSM first, then dense HMMA burst
            uint32_t bb[4][4];
#pragma unroll
            for (int j = 0; j < 4; j++)
                ldmatrix_x4(bb[j], Bsm + (bBase[j] ^ kOff));
            uint32_t a[2][4];
#pragma unroll
            for (int mt = 0; mt < 2; mt++)
                ldmatrix_x4(a[mt], Asm + (aBase[mt] ^ kOff));
#pragma unroll
            for (int j = 0; j < 4; j++)
#pragma unroll
                for (int mt = 0; mt < 2; mt++) {
                    mma16816(acc[mt][2 * j + 0], a[mt], bb[j][0], bb[j][1]);
                    mma16816(acc[mt][2 * j + 1], a[mt], bb[j][2], bb[j][3]);
                }
        }
    };

    // ---- pipelined mainloop: 3-stage ring, ONE barrier per stage ----
    loadStage(0, 0); CP_COMMIT;
    loadStage(1, 1); CP_COMMIT;
    int buf = 0, nbuf = 2;
#pragma unroll 1
    for (int s = 0; s < NSTAGES; s++) {
        if (s < NSTAGES - 1) { CP_WAIT1; } else { CP_WAIT0; }   // stage s resident
        __syncthreads();   // data visible to all; all warps done with stage s-1 (buf being reloaded)
        if (s + 2 < NSTAGES) {
            loadStage(s + 2, nbuf);
            CP_COMMIT;
        }
        computeStage(buf);
        buf = (buf + 1 == PIPE) ? 0 : buf + 1;
        nbuf = (nbuf + 1 == PIPE) ? 0 : nbuf + 1;
    }

    // ---- epilogue ----
    const int rbase = blockIdx.x * MTILE + mwb + (L >> 2);
    const int cbase = nTileBase + nwb + (L & 3) * 2;
#pragma unroll
    for (int mt = 0; mt < 2; mt++) {
        const int r0 = rbase + mt * 16;
        const int r1 = r0 + 8;
#pragma unroll
        for (int nf = 0; nf < 8; nf++) {
            const int col = cbase + nf * 8;
            float2 bb = *reinterpret_cast<const float2*>(bias + col);
            float c0 = acc[mt][nf][0] + bb.x;
            float c1 = acc[mt][nf][1] + bb.y;
            float c2 = acc[mt][nf][2] + bb.x;
            float c3 = acc[mt][nf][3] + bb.y;
            if (CONV == 2) {
                float2 x0 = *reinterpret_cast<const float2*>(xres + (size_t)r0 * CCH + col);
                float2 x1 = *reinterpret_cast<const float2*>(xres + (size_t)r1 * CCH + col);
                c0 += x0.x; c1 += x0.y; c2 += x1.x; c3 += x1.y;
            }
            c0 = leaky(c0); c1 = leaky(c1); c2 = leaky(c2); c3 = leaky(c3);
            if (CONV == 1) {
                *reinterpret_cast<uint32_t*>(g_h + (size_t)r0 * CCH + col) = pack_h2(c0, c1);
                *reinterpret_cast<uint32_t*>(g_h + (size_t)r1 * CCH + col) = pack_h2(c2, c3);
            } else {
                *reinterpret_cast<float2*>(outp + (size_t)r0 * CCH + col) = make_float2(c0, c1);
                *reinterpret_cast<float2*>(outp + (size_t)r1 * CCH + col) = make_float2(c2, c3);
            }
        }
    }
}

// ---------------- launch ----------------
extern "C" void kernel_launch(void* const* d_in, const int* in_sizes, int n_in,
                              void* d_out, int out_size) {
    const float* x  = (const float*)d_in[0];
    const float* W1 = (const float*)d_in[1];
    const float* b1 = (const float*)d_in[2];
    const float* W2 = (const float*)d_in[3];
    const float* b2 = (const float*)d_in[4];
    float* out = (float*)d_out;
    (void)in_sizes; (void)n_in; (void)out_size;

    cudaFuncSetAttribute(hexconv_kernel<1>, cudaFuncAttributeMaxDynamicSharedMemorySize, SMEM_BYTES);
    cudaFuncSetAttribute(hexconv_kernel<2>, cudaFuncAttributeMaxDynamicSharedMemorySize, SMEM_BYTES);

    // resolve device-global addresses for the gather sources
    __half* xh = nullptr; __half* h = nullptr;
    cudaGetSymbolAddress((void**)&xh, g_xh);
    cudaGetSymbolAddress((void**)&h,  g_h);

    prep_weights<<<(KTOT * CCH + 255) / 256, 256>>>(W1, W2);
    convert_x<<<(MTOT * CCH / 4) / 256, 256>>>(x);

    dim3 grid(MTILES, 2);
    hexconv_kernel<1><<<grid, 256, SMEM_BYTES>>>(xh, b1, nullptr, nullptr);
    hexconv_kernel<2><<<grid, 256, SMEM_BYTES>>>(h,  b2, x, out);
}

// round 14
// speedup vs baseline: 1.2844x; 1.2844x over previous
#include <cuda_runtime.h>
#include <cuda_fp16.h>
#include <cstdint>

// ---------------- problem constants ----------------
#define B_SZ   1024
#define NPOS   165
#define CCH    256
#define KTOT   1792            // 7 * 256
#define MTOT   (B_SZ * NPOS)   // 168960
#define MTILE  128
#define NTILE  128
#define MTILES (MTOT / MTILE)  // 1320 (exact)
#define KSTAGE 64
#define NSTAGES (KTOT / KSTAGE) // 28

// smem: A bufs 2x16KB @0, B bufs 2x16KB @32768
#define SMEM_BYTES 65536

// ---------------- device globals (scratch; no runtime allocs) ----------------
__device__ __align__(16) __half g_Wt1[CCH * KTOT];
__device__ __align__(16) __half g_Wt2[CCH * KTOT];
__device__ __align__(16) __half g_xh[(size_t)MTOT * CCH];
__device__ __align__(16) __half g_h [(size_t)MTOT * CCH];

// hex neighbor offsets (0-based grid coords). DY same for both parities.
__constant__ int cDY[7]  = {-1,-1, 0,0,0, 1,1};
__constant__ int cDX0[7] = {-1, 0,-1,0,1,-1,0};  // y even (0-based)
__constant__ int cDX1[7] = { 0, 1,-1,0,1, 0,1};  // y odd  (0-based)

// ---------------- helpers ----------------
__device__ __forceinline__ uint32_t smem_to_u32(const void* p) {
    uint32_t a;
    asm("{ .reg .u64 t; cvta.to.shared.u64 t, %1; cvt.u32.u64 %0, t; }" : "=r"(a) : "l"(p));
    return a;
}
__device__ __forceinline__ void cp_async16(uint32_t dst, const void* src, uint32_t srcsize) {
    asm volatile("cp.async.cg.shared.global [%0], [%1], 16, %2;"
                 :: "r"(dst), "l"(src), "r"(srcsize));
}
#define CP_COMMIT  asm volatile("cp.async.commit_group;")
#define CP_WAIT0   asm volatile("cp.async.wait_group 0;")

__device__ __forceinline__ void ldmatrix_x4(uint32_t* r, uint32_t addr) {
    asm volatile("ldmatrix.sync.aligned.m8n8.x4.shared.b16 {%0,%1,%2,%3}, [%4];"
                 : "=r"(r[0]), "=r"(r[1]), "=r"(r[2]), "=r"(r[3]) : "r"(addr));
}
__device__ __forceinline__ void mma16816(float* c, const uint32_t* a, uint32_t b0, uint32_t b1) {
    asm volatile("mma.sync.aligned.m16n8k16.row.col.f32.f16.f16.f32 "
                 "{%0,%1,%2,%3}, {%4,%5,%6,%7}, {%8,%9}, {%0,%1,%2,%3};"
                 : "+f"(c[0]), "+f"(c[1]), "+f"(c[2]), "+f"(c[3])
                 : "r"(a[0]), "r"(a[1]), "r"(a[2]), "r"(a[3]), "r"(b0), "r"(b1));
}
__device__ __forceinline__ uint32_t pack_h2(float a, float b) {
    __half2 h = __floats2half2_rn(a, b);
    return *reinterpret_cast<uint32_t*>(&h);
}
__device__ __forceinline__ float leaky(float v) { return v > 0.0f ? v : 0.01f * v; }

// ---------------- prep kernels ----------------
__global__ void prep_weights(const float* __restrict__ W1, const float* __restrict__ W2) {
    int i = blockIdx.x * 256 + threadIdx.x;
    if (i < KTOT * CCH) {
        int k = i >> 8, n = i & 255;
        g_Wt1[n * KTOT + k] = __float2half_rn(W1[i]);
        g_Wt2[n * KTOT + k] = __float2half_rn(W2[i]);
    }
}
__global__ void convert_x(const float* __restrict__ x) {
    size_t i = (size_t)blockIdx.x * 256 + threadIdx.x;   // one float4 each
    float4 f = reinterpret_cast<const float4*>(x)[i];
    uint2 o;
    o.x = pack_h2(f.x, f.y);
    o.y = pack_h2(f.z, f.w);
    reinterpret_cast<uint2*>(g_xh)[i] = o;
}

// ---------------- fused hexconv GEMM (mma.sync path) ----------------
// CONV==1: A = g_xh, out = leaky(acc + b1) -> g_h (fp16)
// CONV==2: A = g_h,  out = leaky(acc + b2 + x) -> fp32 d_out
template <int CONV>
__global__ void __launch_bounds__(256, 2)
hexconv_kernel(const __half* __restrict__ asrc, const float* __restrict__ bias,
               const float* __restrict__ xres, float* __restrict__ outp) {
    extern __shared__ char smem[];
    const uint32_t sb = smem_to_u32(smem);
    const int tid = threadIdx.x;
    const int wid = tid >> 5, L = tid & 31;
    const int lane8 = tid & 7;      // 16B column within 128B row
    const int rowslot = tid >> 3;   // 32 rows per pass

    // ---- loader geometry: 4 rows per thread for both A (gather) and B ----
    int pb[4], yy[4], xx[4];
    uint32_t rswz[4];
#pragma unroll
    for (int j = 0; j < 4; j++) {
        int i = rowslot + 32 * j;
        int r = blockIdx.x * MTILE + i;
        int b = r / NPOS;
        int p = r - b * NPOS;
        pb[j] = b * NPOS;
        yy[j] = p / 15;
        xx[j] = p - yy[j] * 15;
        uint32_t off = (uint32_t)i * 128u + (uint32_t)lane8 * 16u;
        rswz[j] = off ^ ((off >> 3) & 0x70u);
    }
    const __half* __restrict__ Wt = (CONV == 1) ? g_Wt1 : g_Wt2;
    const int nTileBase = blockIdx.y * NTILE;

    // ---- compute-side ldmatrix lane addressing ----
    // warps: wid%4 -> M (32 rows), wid/4 -> N (64 cols)
    const int mwb = (wid & 3) * 32;
    const int nwb = (wid >> 2) * 64;
    const uint32_t rowA  = (uint32_t)(mwb + (L & 7) + ((L & 8) ? 8 : 0));
    const uint32_t kbitA = (uint32_t)((L >> 4) & 1);
    uint32_t rowB[4];
#pragma unroll
    for (int j = 0; j < 4; j++)
        rowB[j] = (uint32_t)(nwb + j * 16 + (L & 7) + ((L & 16) ? 8 : 0));
    const uint32_t kbitB = (uint32_t)((L >> 3) & 1);

    float acc[2][8][4];
#pragma unroll
    for (int mt = 0; mt < 2; mt++)
#pragma unroll
        for (int nf = 0; nf < 8; nf++)
#pragma unroll
            for (int q = 0; q < 4; q++) acc[mt][nf][q] = 0.0f;

    // ---- stage loader (cp.async, zero-fill for out-of-grid neighbors) ----
    auto loadStage = [&](int s, int buf) {
        const uint32_t Asm = sb + (uint32_t)buf * 16384u;
        const uint32_t Bsm = sb + 32768u + (uint32_t)buf * 16384u;
        // B: W rows nTileBase+n, k in [s*64, s*64+64)
        const __half* wk = Wt + s * KSTAGE + lane8 * 8;
#pragma unroll
        for (int j = 0; j < 4; j++) {
            int n = nTileBase + rowslot + 32 * j;
            cp_async16(Bsm + rswz[j], wk + (size_t)n * KTOT, 16u);
        }
        // A: hex gather, tap = s>>2, channels (s&3)*64 ..
        const int tap = s >> 2;
        const int cc = ((s & 3) << 6) + lane8 * 8;
        const int dy = cDY[tap];
#pragma unroll
        for (int j = 0; j < 4; j++) {
            int ny = yy[j] + dy;
            int nx = xx[j] + ((yy[j] & 1) ? cDX1[tap] : cDX0[tap]);
            bool v = ((unsigned)ny < 11u) && ((unsigned)nx < 15u);
            int nrow = v ? (pb[j] + ny * 15 + nx) : 0;
            cp_async16(Asm + rswz[j], asrc + (size_t)nrow * CCH + cc, v ? 16u : 0u);
        }
    };

    // ---- stage compute: 4 x k16 steps of m16n8k16 (R8 interleaved form) ----
    auto computeStage = [&](int buf) {
        const uint32_t Asm = sb + (uint32_t)buf * 16384u;
        const uint32_t Bsm = sb + 32768u + (uint32_t)buf * 16384u;
#pragma unroll
        for (int k = 0; k < 4; k++) {
            uint32_t a[2][4];
#pragma unroll
            for (int mt = 0; mt < 2; mt++) {
                uint32_t row = rowA + (uint32_t)mt * 16u;
                uint32_t kq = 2u * (uint32_t)k + kbitA;
                uint32_t ad = Asm + row * 128u + ((kq * 16u) ^ ((row & 7u) << 4));
                ldmatrix_x4(a[mt], ad);
            }
#pragma unroll
            for (int j = 0; j < 4; j++) {
                uint32_t row = rowB[j];
                uint32_t kq = 2u * (uint32_t)k + kbitB;
                uint32_t bd = Bsm + row * 128u + ((kq * 16u) ^ ((row & 7u) << 4));
                uint32_t bb[4];
                ldmatrix_x4(bb, bd);
#pragma unroll
                for (int mt = 0; mt < 2; mt++) {
                    mma16816(acc[mt][2 * j + 0], a[mt], bb[0], bb[1]);
                    mma16816(acc[mt][2 * j + 1], a[mt], bb[2], bb[3]);
                }
            }
        }
    };

    // ---- pipelined mainloop: double buffer, ONE barrier per stage ----
    // iter s: wait(group s) -> sync (publish s; retire readers of buf (s+1)&1)
    //         -> issue load(s+1) into buf (s+1)&1 -> compute(s) on buf s&1
    loadStage(0, 0);
    CP_COMMIT;
#pragma unroll 1
    for (int s = 0; s < NSTAGES; s++) {
        CP_WAIT0;          // stage s fully resident (also empties queue)
        __syncthreads();   // publish stage s; all warps done with stage s-1
        if (s + 1 < NSTAGES) {
            loadStage(s + 1, (s + 1) & 1);
            CP_COMMIT;     // overlaps with compute(s) below
        }
        computeStage(s & 1);
    }

    // ---- epilogue ----
    const int rbase = blockIdx.x * MTILE + mwb + (L >> 2);
    const int cbase = nTileBase + nwb + (L & 3) * 2;
#pragma unroll
    for (int mt = 0; mt < 2; mt++) {
        const int r0 = rbase + mt * 16;
        const int r1 = r0 + 8;
#pragma unroll
        for (int nf = 0; nf < 8; nf++) {
            const int col = cbase + nf * 8;
            float2 bb = *reinterpret_cast<const float2*>(bias + col);
            float c0 = acc[mt][nf][0] + bb.x;
            float c1 = acc[mt][nf][1] + bb.y;
            float c2 = acc[mt][nf][2] + bb.x;
            float c3 = acc[mt][nf][3] + bb.y;
            if (CONV == 2) {
                float2 x0 = *reinterpret_cast<const float2*>(xres + (size_t)r0 * CCH + col);
                float2 x1 = *reinterpret_cast<const float2*>(xres + (size_t)r1 * CCH + col);
                c0 += x0.x; c1 += x0.y; c2 += x1.x; c3 += x1.y;
            }
            c0 = leaky(c0); c1 = leaky(c1); c2 = leaky(c2); c3 = leaky(c3);
            if (CONV == 1) {
                *reinterpret_cast<uint32_t*>(g_h + (size_t)r0 * CCH + col) = pack_h2(c0, c1);
                *reinterpret_cast<uint32_t*>(g_h + (size_t)r1 * CCH + col) = pack_h2(c2, c3);
            } else {
                *reinterpret_cast<float2*>(outp + (size_t)r0 * CCH + col) = make_float2(c0, c1);
                *reinterpret_cast<float2*>(outp + (size_t)r1 * CCH + col) = make_float2(c2, c3);
            }
        }
    }
}

// ---------------- launch ----------------
extern "C" void kernel_launch(void* const* d_in, const int* in_sizes, int n_in,
                              void* d_out, int out_size) {
    const float* x  = (const float*)d_in[0];
    const float* W1 = (const float*)d_in[1];
    const float* b1 = (const float*)d_in[2];
    const float* W2 = (const float*)d_in[3];
    const float* b2 = (const float*)d_in[4];
    float* out = (float*)d_out;
    (void)in_sizes; (void)n_in; (void)out_size;

    cudaFuncSetAttribute(hexconv_kernel<1>, cudaFuncAttributeMaxDynamicSharedMemorySize, SMEM_BYTES);
    cudaFuncSetAttribute(hexconv_kernel<2>, cudaFuncAttributeMaxDynamicSharedMemorySize, SMEM_BYTES);

    // resolve device-global addresses for the gather sources
    __half* xh = nullptr; __half* h = nullptr;
    cudaGetSymbolAddress((void**)&xh, g_xh);
    cudaGetSymbolAddress((void**)&h,  g_h);

    prep_weights<<<(KTOT * CCH + 255) / 256, 256>>>(W1, W2);
    convert_x<<<(MTOT * CCH / 4) / 256, 256>>>(x);

    dim3 grid(MTILES, 2);
    hexconv_kernel<1><<<grid, 256, SMEM_BYTES>>>(xh, b1, nullptr, nullptr);
    hexconv_kernel<2><<<grid, 256, SMEM_BYTES>>>(h,  b2, x, out);
}